// round 8
// baseline (speedup 1.0000x reference)
#include <cuda_runtime.h>
#include <math.h>
#include <stdint.h>

// Problem constants
#define BB   4
#define NN   2000
#define KKN  30
#define DD   128
#define DIN  256
#define HH   4
#define ROWS (BB*NN)           // 8000

#define SCALE 0.17677669529663687f   // 1/sqrt(32)

// k2 pipeline config
#define R2       8                    // rows per k2 block
#define EFLOATS  (KKN*DIN)            // 7680 floats per E tile
#define QFLOATS  (HH*DIN)             // 1024 floats per Qp row
// dynamic smem layout (in floats)
#define OFF_E    0                    // 2 * 7680
#define OFF_Q    (2*EFLOATS)          // 15360: 2 * 1024
#define OFF_LG   (OFF_Q + 2*QFLOATS)  // 17408: 4*32
#define OFF_WS   (OFF_LG + 128)       // 17536: 30*4 (pad to 128)
#define OFF_MS   (OFF_WS + 128)       // 17664: 8*32 ints
#define SMEM_FLOATS (OFF_MS + 256)    // 17920 floats = 71680 B
#define K2_SMEM_BYTES (SMEM_FLOATS*4)

// Scratch (static device globals: no runtime allocation)
__device__ float g_Q   [(size_t)ROWS*DD];      //  4 MB  Q = hV @ WQ^T
__device__ float g_Qp  [(size_t)ROWS*HH*DIN];  // 32 MB  per-head K-projected query
__device__ float g_Eagg[(size_t)ROWS*HH*DIN];  // 32 MB  softmax-weighted E aggregate
__device__ float g_hu  [(size_t)ROWS*DD];      //  4 MB  per-head V projection

__device__ __forceinline__ void cp16(uint32_t dst_smem, const void* src) {
    asm volatile("cp.async.cg.shared.global [%0], [%1], 16;" :: "r"(dst_smem), "l"(src));
}
__device__ __forceinline__ void cp_commit() {
    asm volatile("cp.async.commit_group;");
}
__device__ __forceinline__ void cp_wait0() {
    asm volatile("cp.async.wait_group 0;" ::: "memory");
}

// ---------------------------------------------------------------------------
// Kernel Q: Q[r][j] = sum_d hV[r][d] * WQ[j][d].   grid (125, 4)
// 64x32 tile, 256 threads, acc[4][2], register double-buffered staging.
// ---------------------------------------------------------------------------
__global__ __launch_bounds__(256) void kQ(const float* __restrict__ hV,
                                          const float* __restrict__ WQ)
{
    __shared__ float as[64*33];
    __shared__ float bs[32*33];

    const int tid  = threadIdx.x;
    const int row0 = blockIdx.x * 64;
    const int col0 = blockIdx.y * 32;
    const int rt   = tid >> 4;
    const int jt   = tid & 15;

    float ra[8], rb[4];
    #pragma unroll
    for (int it = 0; it < 8; it++) {
        int i = tid + 256*it;
        ra[it] = hV[(size_t)(row0 + (i >> 5))*DD + (i & 31)];
    }
    #pragma unroll
    for (int it = 0; it < 4; it++) {
        int i = tid + 256*it;
        rb[it] = WQ[(size_t)(col0 + (i >> 5))*DD + (i & 31)];
    }

    float acc[4][2] = {};
    for (int dc = 0; dc < DD; dc += 32) {
        __syncthreads();
        #pragma unroll
        for (int it = 0; it < 8; it++) {
            int i = tid + 256*it;
            as[(i >> 5)*33 + (i & 31)] = ra[it];
        }
        #pragma unroll
        for (int it = 0; it < 4; it++) {
            int i = tid + 256*it;
            bs[(i >> 5)*33 + (i & 31)] = rb[it];
        }
        __syncthreads();
        if (dc + 32 < DD) {
            #pragma unroll
            for (int it = 0; it < 8; it++) {
                int i = tid + 256*it;
                ra[it] = hV[(size_t)(row0 + (i >> 5))*DD + dc + 32 + (i & 31)];
            }
            #pragma unroll
            for (int it = 0; it < 4; it++) {
                int i = tid + 256*it;
                rb[it] = WQ[(size_t)(col0 + (i >> 5))*DD + dc + 32 + (i & 31)];
            }
        }
        #pragma unroll
        for (int c = 0; c < 32; c++) {
            float a[4], b[2];
            #pragma unroll
            for (int m = 0; m < 4; m++) a[m] = as[(rt + 16*m)*33 + c];
            #pragma unroll
            for (int n = 0; n < 2; n++) b[n] = bs[(jt + 16*n)*33 + c];
            #pragma unroll
            for (int m = 0; m < 4; m++)
                #pragma unroll
                for (int n = 0; n < 2; n++) acc[m][n] += a[m]*b[n];
        }
    }
    #pragma unroll
    for (int m = 0; m < 4; m++)
        #pragma unroll
        for (int n = 0; n < 2; n++)
            g_Q[(size_t)(row0 + rt + 16*m)*DD + col0 + jt + 16*n] = acc[m][n];
}

// ---------------------------------------------------------------------------
// Kernel Qp: per head h, Qp[r][h*256+c] = SCALE * sum_{j<32} Q[r][h*32+j]*WK[h*32+j][c]
// Block: 64 rows x (4 chunks of 64 cols), 256 threads, 4x4 tile, Q staged ONCE.
// grid (125, 4 heads)
// ---------------------------------------------------------------------------
__global__ __launch_bounds__(256) void kQp(const float* __restrict__ WK)
{
    __shared__ float qs[64*33];    // [r][j]  j<32  (staged once)
    __shared__ float ws[32*65];    // [j][c]  c<64  (per chunk)

    const int tid  = threadIdx.x;
    const int row0 = blockIdx.x * 64;
    const int h    = blockIdx.y;
    const int rt   = tid >> 4;
    const int ct   = tid & 15;

    {
        int i = tid;
        #pragma unroll
        for (int it = 0; it < 8; it++, i += 256) {
            int r = i >> 5, j = i & 31;
            qs[r*33 + j] = g_Q[(size_t)(row0 + r)*DD + h*32 + j];
        }
    }

    for (int cc = 0; cc < DIN; cc += 64) {
        __syncthreads();
        {
            int i = tid;
            #pragma unroll
            for (int it = 0; it < 8; it++, i += 256) {
                int j = i >> 6, c = i & 63;
                ws[j*65 + c] = WK[(size_t)(h*32 + j)*DIN + cc + c];
            }
        }
        __syncthreads();

        float acc[4][4] = {};
        #pragma unroll
        for (int j = 0; j < 32; j++) {
            float a[4], b[4];
            #pragma unroll
            for (int m = 0; m < 4; m++) a[m] = qs[(rt + 16*m)*33 + j];
            #pragma unroll
            for (int n = 0; n < 4; n++) b[n] = ws[j*65 + ct + 16*n];
            #pragma unroll
            for (int m = 0; m < 4; m++)
                #pragma unroll
                for (int n = 0; n < 4; n++) acc[m][n] += a[m]*b[n];
        }
        #pragma unroll
        for (int m = 0; m < 4; m++)
            #pragma unroll
            for (int n = 0; n < 4; n++)
                g_Qp[(size_t)(row0 + rt + 16*m)*(HH*DIN) + h*DIN + cc + ct + 16*n]
                    = acc[m][n] * SCALE;
    }
}

// ---------------------------------------------------------------------------
// Kernel 2 (pipelined): 8 rows per block, cp.async double-buffered E + Qp.
// Per row: logits -> masked softmax -> weighted E aggregation -> g_Eagg.
// grid 1000, 256 threads, 72 KB dynamic smem.
// ---------------------------------------------------------------------------
__global__ __launch_bounds__(256) void k2_attn(const float* __restrict__ hE,
                                               const int*   __restrict__ mask)
{
    extern __shared__ __align__(16) float sm[];
    float* Eb = sm + OFF_E;        // [2][7680]
    float* Qb = sm + OFF_Q;        // [2][1024]
    float* lg = sm + OFF_LG;       // [4][32]
    float* ws = sm + OFF_WS;       // [30][4]
    int*   ms = (int*)(sm + OFF_MS); // [8][32]

    const int tid  = threadIdx.x;
    const int row0 = blockIdx.x * R2;
    const int warp = tid >> 5, lane = tid & 31;

    // masks for all 8 rows (plain loads; consumed after first sync)
    if (tid < R2*KKN) {
        int r = tid / KKN, k = tid - r*KKN;
        ms[r*32 + k] = mask[(row0 + r)*KKN + k];
    }

    // prefetch row 0 into buffer 0
    {
        uint32_t se = (uint32_t)__cvta_generic_to_shared(Eb);
        const float* src = hE + (size_t)row0 * EFLOATS;
        for (int i = tid; i < EFLOATS/4; i += 256) cp16(se + i*16, src + i*4);
        uint32_t sq = (uint32_t)__cvta_generic_to_shared(Qb);
        const float* qsrc = g_Qp + (size_t)row0 * QFLOATS;
        if (tid < QFLOATS/4) cp16(sq + tid*16, qsrc + tid*4);
    }
    cp_commit();

    for (int r = 0; r < R2; r++) {
        const int b = r & 1;
        float* Es = Eb + b * EFLOATS;
        float* Qs = Qb + b * QFLOATS;

        cp_wait0();
        __syncthreads();   // buffer b ready; all threads done with buffer 1-b

        // prefetch row r+1 into buffer 1-b (overlaps compute below)
        if (r + 1 < R2) {
            float* En = Eb + (1 - b) * EFLOATS;
            float* Qn = Qb + (1 - b) * QFLOATS;
            uint32_t se = (uint32_t)__cvta_generic_to_shared(En);
            const float* src = hE + (size_t)(row0 + r + 1) * EFLOATS;
            for (int i = tid; i < EFLOATS/4; i += 256) cp16(se + i*16, src + i*4);
            uint32_t sq = (uint32_t)__cvta_generic_to_shared(Qn);
            const float* qsrc = g_Qp + (size_t)(row0 + r + 1) * QFLOATS;
            if (tid < QFLOATS/4) cp16(sq + tid*16, qsrc + tid*4);
            cp_commit();
        }

        // ---- logits: 120 warp-collective dots of length 256 ----
        for (int idx = warp; idx < HH*KKN; idx += 8) {
            int h = idx / KKN, k = idx - h*KKN;
            const float4* e4 = (const float4*)(Es + k*DIN);
            const float4* q4 = (const float4*)(Qs + h*DIN);
            float4 ea = e4[lane*2], eb2 = e4[lane*2 + 1];
            float4 qa = q4[lane*2], qb2 = q4[lane*2 + 1];
            float s = ea.x*qa.x + ea.y*qa.y + ea.z*qa.z + ea.w*qa.w
                    + eb2.x*qb2.x + eb2.y*qb2.y + eb2.z*qb2.z + eb2.w*qb2.w;
            #pragma unroll
            for (int off = 16; off; off >>= 1) s += __shfl_xor_sync(0xffffffffu, s, off);
            if (lane == 0) lg[h*32 + k] = s;
        }
        __syncthreads();

        // ---- masked softmax per head (one warp per head) ----
        if (warp < HH) {
            int   m = 0;
            float v = -3.0e38f;
            if (lane < KKN) { m = ms[r*32 + lane]; v = m ? lg[warp*32 + lane] : -3.0e38f; }
            float mx = v;
            #pragma unroll
            for (int off = 16; off; off >>= 1) mx = fmaxf(mx, __shfl_xor_sync(0xffffffffu, mx, off));
            float e  = (lane < KKN) ? expf(v - mx) : 0.f;
            float smv = e;
            #pragma unroll
            for (int off = 16; off; off >>= 1) smv += __shfl_xor_sync(0xffffffffu, smv, off);
            if (lane < KKN) ws[lane*4 + warp] = (e / smv) * (float)m;
        }
        __syncthreads();

        // ---- aggregation: Eagg[h][c] = sum_k w[h][k] * E[k][c] ----
        {
            const int c = tid;  // 0..255
            float acc0 = 0.f, acc1 = 0.f, acc2 = 0.f, acc3 = 0.f;
            #pragma unroll 5
            for (int k = 0; k < KKN; k++) {
                float4 w  = *(const float4*)&ws[k*4];
                float  ev = Es[k*DIN + c];
                acc0 += w.x * ev; acc1 += w.y * ev; acc2 += w.z * ev; acc3 += w.w * ev;
            }
            float* out = g_Eagg + (size_t)(row0 + r) * QFLOATS;
            out[0*DIN + c] = acc0;
            out[1*DIN + c] = acc1;
            out[2*DIN + c] = acc2;
            out[3*DIN + c] = acc3;
        }
        // next iteration's cp_wait0 + __syncthreads covers lg/ws/buffer reuse
    }
}

// ---------------------------------------------------------------------------
// Kernel 3: hu[r][h*32+j] = sum_c WV[h*32+j][c] * Eagg[r][h][c]
// 64 rows x 32 j (one head), 256 threads, acc[4][2], double-buffered.
// grid (125, 4 heads)
// ---------------------------------------------------------------------------
__global__ __launch_bounds__(256) void k3_vproj(const float* __restrict__ WV)
{
    __shared__ float as[64*33];
    __shared__ float bs[32*33];

    const int tid  = threadIdx.x;
    const int row0 = blockIdx.x * 64;
    const int h    = blockIdx.y;
    const int rt   = tid >> 4;
    const int jt   = tid & 15;

    const float* A  = g_Eagg + (size_t)h * DIN;
    const float* Bw = WV + (size_t)h * 32 * DIN;

    float ra[8], rb[4];
    #pragma unroll
    for (int it = 0; it < 8; it++) {
        int i = tid + 256*it;
        ra[it] = A[(size_t)(row0 + (i >> 5))*(HH*DIN) + (i & 31)];
    }
    #pragma unroll
    for (int it = 0; it < 4; it++) {
        int i = tid + 256*it;
        rb[it] = Bw[(size_t)(i >> 5)*DIN + (i & 31)];
    }

    float acc[4][2] = {};
    for (int cc = 0; cc < DIN; cc += 32) {
        __syncthreads();
        #pragma unroll
        for (int it = 0; it < 8; it++) {
            int i = tid + 256*it;
            as[(i >> 5)*33 + (i & 31)] = ra[it];
        }
        #pragma unroll
        for (int it = 0; it < 4; it++) {
            int i = tid + 256*it;
            bs[(i >> 5)*33 + (i & 31)] = rb[it];
        }
        __syncthreads();
        if (cc + 32 < DIN) {
            #pragma unroll
            for (int it = 0; it < 8; it++) {
                int i = tid + 256*it;
                ra[it] = A[(size_t)(row0 + (i >> 5))*(HH*DIN) + cc + 32 + (i & 31)];
            }
            #pragma unroll
            for (int it = 0; it < 4; it++) {
                int i = tid + 256*it;
                rb[it] = Bw[(size_t)(i >> 5)*DIN + cc + 32 + (i & 31)];
            }
        }
        #pragma unroll
        for (int c = 0; c < 32; c++) {
            float a[4], b[2];
            #pragma unroll
            for (int m = 0; m < 4; m++) a[m] = as[(rt + 16*m)*33 + c];
            #pragma unroll
            for (int n = 0; n < 2; n++) b[n] = bs[(jt + 16*n)*33 + c];
            #pragma unroll
            for (int m = 0; m < 4; m++)
                #pragma unroll
                for (int n = 0; n < 2; n++) acc[m][n] += a[m]*b[n];
        }
    }
    #pragma unroll
    for (int m = 0; m < 4; m++)
        #pragma unroll
        for (int n = 0; n < 2; n++)
            g_hu[(size_t)(row0 + rt + 16*m)*DD + h*32 + jt + 16*n] = acc[m][n];
}

// ---------------------------------------------------------------------------
// Kernel 4: out[r][o] = sum_d hu[r][d] * WO[o][d]
// 64 rows x 32 cols, grid (125, 4), double-buffered.
// ---------------------------------------------------------------------------
__global__ __launch_bounds__(256) void k4_out(const float* __restrict__ WO,
                                              float* __restrict__ out)
{
    __shared__ float as[64*33];
    __shared__ float bs[32*33];

    const int tid  = threadIdx.x;
    const int row0 = blockIdx.x * 64;
    const int col0 = blockIdx.y * 32;
    const int rt   = tid >> 4;
    const int jt   = tid & 15;

    float ra[8], rb[4];
    #pragma unroll
    for (int it = 0; it < 8; it++) {
        int i = tid + 256*it;
        ra[it] = g_hu[(size_t)(row0 + (i >> 5))*DD + (i & 31)];
    }
    #pragma unroll
    for (int it = 0; it < 4; it++) {
        int i = tid + 256*it;
        rb[it] = WO[(size_t)(col0 + (i >> 5))*DD + (i & 31)];
    }

    float acc[4][2] = {};
    for (int dc = 0; dc < DD; dc += 32) {
        __syncthreads();
        #pragma unroll
        for (int it = 0; it < 8; it++) {
            int i = tid + 256*it;
            as[(i >> 5)*33 + (i & 31)] = ra[it];
        }
        #pragma unroll
        for (int it = 0; it < 4; it++) {
            int i = tid + 256*it;
            bs[(i >> 5)*33 + (i & 31)] = rb[it];
        }
        __syncthreads();
        if (dc + 32 < DD) {
            #pragma unroll
            for (int it = 0; it < 8; it++) {
                int i = tid + 256*it;
                ra[it] = g_hu[(size_t)(row0 + (i >> 5))*DD + dc + 32 + (i & 31)];
            }
            #pragma unroll
            for (int it = 0; it < 4; it++) {
                int i = tid + 256*it;
                rb[it] = WO[(size_t)(col0 + (i >> 5))*DD + dc + 32 + (i & 31)];
            }
        }
        #pragma unroll
        for (int c = 0; c < 32; c++) {
            float a[4], b[2];
            #pragma unroll
            for (int m = 0; m < 4; m++) a[m] = as[(rt + 16*m)*33 + c];
            #pragma unroll
            for (int n = 0; n < 2; n++) b[n] = bs[(jt + 16*n)*33 + c];
            #pragma unroll
            for (int m = 0; m < 4; m++)
                #pragma unroll
                for (int n = 0; n < 2; n++) acc[m][n] += a[m]*b[n];
        }
    }
    #pragma unroll
    for (int m = 0; m < 4; m++)
        #pragma unroll
        for (int n = 0; n < 2; n++)
            out[(size_t)(row0 + rt + 16*m)*DD + col0 + jt + 16*n] = acc[m][n];
}

// ---------------------------------------------------------------------------
extern "C" void kernel_launch(void* const* d_in, const int* in_sizes, int n_in,
                              void* d_out, int out_size)
{
    const float* hV   = (const float*)d_in[0];
    const float* hE   = (const float*)d_in[1];
    const int*   mask = (const int*)  d_in[2];
    const float* WQ   = (const float*)d_in[3];
    const float* WK   = (const float*)d_in[4];
    const float* WV   = (const float*)d_in[5];
    const float* WO   = (const float*)d_in[6];
    float*       out  = (float*)d_out;

    cudaFuncSetAttribute(k2_attn, cudaFuncAttributeMaxDynamicSharedMemorySize,
                         K2_SMEM_BYTES);

    kQ     <<<dim3(ROWS/64, 4),   256>>>(hV, WQ);
    kQp    <<<dim3(ROWS/64, HH),  256>>>(WK);
    k2_attn<<<ROWS/R2, 256, K2_SMEM_BYTES>>>(hE, mask);
    k3_vproj<<<dim3(ROWS/64, HH), 256>>>(WV);
    k4_out <<<dim3(ROWS/64, 4),   256>>>(WO, out);
}

// round 11
// speedup vs baseline: 1.4257x; 1.4257x over previous
#include <cuda_runtime.h>
#include <math.h>
#include <stdint.h>

// Problem constants
#define BB   4
#define NN   2000
#define KKN  30
#define DD   128
#define DIN  256
#define HH   4
#define ROWS (BB*NN)           // 8000

#define SCALE 0.17677669529663687f   // 1/sqrt(32)

#define EPITCH 260             // padded E row pitch (floats): conflict-free banks
#define QPITCH 260             // padded Q row pitch

// Scratch (static device globals: no runtime allocation)
__device__ float g_Q   [(size_t)ROWS*DD];      //  4 MB  Q = hV @ WQ^T
__device__ float g_Qp  [(size_t)ROWS*HH*DIN];  // 32 MB  per-head K-projected query
__device__ float g_Eagg[(size_t)ROWS*HH*DIN];  // 32 MB  softmax-weighted E aggregate
__device__ float g_hu  [(size_t)ROWS*DD];      //  4 MB  per-head V projection

// ---------------------------------------------------------------------------
// Kernel Q: Q[r][j] = sum_d hV[r][d] * WQ[j][d].   grid (125, 4)
// 64x32 tile, 256 threads, acc[4][2], register double-buffered staging.
// ---------------------------------------------------------------------------
__global__ __launch_bounds__(256) void kQ(const float* __restrict__ hV,
                                          const float* __restrict__ WQ)
{
    __shared__ float as[64*33];
    __shared__ float bs[32*33];

    const int tid  = threadIdx.x;
    const int row0 = blockIdx.x * 64;
    const int col0 = blockIdx.y * 32;
    const int rt   = tid >> 4;
    const int jt   = tid & 15;

    float ra[8], rb[4];
    #pragma unroll
    for (int it = 0; it < 8; it++) {
        int i = tid + 256*it;
        ra[it] = hV[(size_t)(row0 + (i >> 5))*DD + (i & 31)];
    }
    #pragma unroll
    for (int it = 0; it < 4; it++) {
        int i = tid + 256*it;
        rb[it] = WQ[(size_t)(col0 + (i >> 5))*DD + (i & 31)];
    }

    float acc[4][2] = {};
    for (int dc = 0; dc < DD; dc += 32) {
        __syncthreads();
        #pragma unroll
        for (int it = 0; it < 8; it++) {
            int i = tid + 256*it;
            as[(i >> 5)*33 + (i & 31)] = ra[it];
        }
        #pragma unroll
        for (int it = 0; it < 4; it++) {
            int i = tid + 256*it;
            bs[(i >> 5)*33 + (i & 31)] = rb[it];
        }
        __syncthreads();
        if (dc + 32 < DD) {
            #pragma unroll
            for (int it = 0; it < 8; it++) {
                int i = tid + 256*it;
                ra[it] = hV[(size_t)(row0 + (i >> 5))*DD + dc + 32 + (i & 31)];
            }
            #pragma unroll
            for (int it = 0; it < 4; it++) {
                int i = tid + 256*it;
                rb[it] = WQ[(size_t)(col0 + (i >> 5))*DD + dc + 32 + (i & 31)];
            }
        }
        #pragma unroll
        for (int c = 0; c < 32; c++) {
            float a[4], b[2];
            #pragma unroll
            for (int m = 0; m < 4; m++) a[m] = as[(rt + 16*m)*33 + c];
            #pragma unroll
            for (int n = 0; n < 2; n++) b[n] = bs[(jt + 16*n)*33 + c];
            #pragma unroll
            for (int m = 0; m < 4; m++)
                #pragma unroll
                for (int n = 0; n < 2; n++) acc[m][n] += a[m]*b[n];
        }
    }
    #pragma unroll
    for (int m = 0; m < 4; m++)
        #pragma unroll
        for (int n = 0; n < 2; n++)
            g_Q[(size_t)(row0 + rt + 16*m)*DD + col0 + jt + 16*n] = acc[m][n];
}

// ---------------------------------------------------------------------------
// Kernel Qp: per head h, Qp[r][h*256+c] = SCALE * sum_{j<32} Q[r][h*32+j]*WK[h*32+j][c]
// Block: 64 rows x (4 chunks of 64 cols), 256 threads, 4x4 tile, Q staged ONCE.
// grid (125, 4 heads)
// ---------------------------------------------------------------------------
__global__ __launch_bounds__(256) void kQp(const float* __restrict__ WK)
{
    __shared__ float qs[64*33];    // [r][j]  j<32  (staged once)
    __shared__ float ws[32*65];    // [j][c]  c<64  (per chunk)

    const int tid  = threadIdx.x;
    const int row0 = blockIdx.x * 64;
    const int h    = blockIdx.y;
    const int rt   = tid >> 4;
    const int ct   = tid & 15;

    {
        int i = tid;
        #pragma unroll
        for (int it = 0; it < 8; it++, i += 256) {
            int r = i >> 5, j = i & 31;
            qs[r*33 + j] = g_Q[(size_t)(row0 + r)*DD + h*32 + j];
        }
    }

    for (int cc = 0; cc < DIN; cc += 64) {
        __syncthreads();
        {
            int i = tid;
            #pragma unroll
            for (int it = 0; it < 8; it++, i += 256) {
                int j = i >> 6, c = i & 63;
                ws[j*65 + c] = WK[(size_t)(h*32 + j)*DIN + cc + c];
            }
        }
        __syncthreads();

        float acc[4][4] = {};
        #pragma unroll
        for (int j = 0; j < 32; j++) {
            float a[4], b[4];
            #pragma unroll
            for (int m = 0; m < 4; m++) a[m] = qs[(rt + 16*m)*33 + j];
            #pragma unroll
            for (int n = 0; n < 4; n++) b[n] = ws[j*65 + ct + 16*n];
            #pragma unroll
            for (int m = 0; m < 4; m++)
                #pragma unroll
                for (int n = 0; n < 4; n++) acc[m][n] += a[m]*b[n];
        }
        #pragma unroll
        for (int m = 0; m < 4; m++)
            #pragma unroll
            for (int n = 0; n < 4; n++)
                g_Qp[(size_t)(row0 + rt + 16*m)*(HH*DIN) + h*DIN + cc + ct + 16*n]
                    = acc[m][n] * SCALE;
    }
}

// ---------------------------------------------------------------------------
// Kernel 2 (shuffle-free): one block per row, 256 threads, 6 blocks/SM.
// E tile -> padded smem (plain float4 loads); logits = thread-per-(k,h)
// private dot (conflict-free banks); masked softmax; aggregation.
// ---------------------------------------------------------------------------
__global__ __launch_bounds__(256) void k2_attn(const float* __restrict__ hE,
                                               const int*   __restrict__ mask)
{
    __shared__ __align__(16) float Es[KKN*EPITCH];  // 30x260
    __shared__ __align__(16) float Qs[HH*QPITCH];   // 4x260
    __shared__ float lg[128];                       // [k*4+h]
    __shared__ __align__(16) float ws[32*4];        // [k][h]
    __shared__ int   ms[32];

    const int tid = threadIdx.x;
    const int row = blockIdx.x;

    // Loads: Qp row + mask first (hide under E stream), then E tile (1920 float4)
    {
        if (tid < (HH*DIN)/4) {
            const float4* Qg = (const float4*)(g_Qp + (size_t)row * (HH*DIN));
            int h = tid >> 6, c4 = tid & 63;
            *(float4*)&Qs[h*QPITCH + c4*4] = Qg[tid];
        }
        if (tid < KKN) ms[tid] = mask[row*KKN + tid];

        const float4* Eg = (const float4*)(hE + (size_t)row * (KKN*DIN));
        #pragma unroll 4
        for (int i = tid; i < (KKN*DIN)/4; i += 256) {
            int k = i >> 6, c4 = i & 63;
            *(float4*)&Es[k*EPITCH + c4*4] = Eg[i];
        }
    }
    __syncthreads();

    // ---- logits: thread t = k*4 + h, private 256-length dot, 4 acc chains ----
    if (tid < HH*KKN) {
        const int k = tid >> 2, h = tid & 3;
        const float4* e4 = (const float4*)(Es + k*EPITCH);
        const float4* q4 = (const float4*)(Qs + h*QPITCH);
        float a0 = 0.f, a1 = 0.f, a2 = 0.f, a3 = 0.f;
        #pragma unroll
        for (int c = 0; c < 64; c += 4) {
            float4 e, q;
            e = e4[c+0]; q = q4[c+0]; a0 += e.x*q.x + e.y*q.y + e.z*q.z + e.w*q.w;
            e = e4[c+1]; q = q4[c+1]; a1 += e.x*q.x + e.y*q.y + e.z*q.z + e.w*q.w;
            e = e4[c+2]; q = q4[c+2]; a2 += e.x*q.x + e.y*q.y + e.z*q.z + e.w*q.w;
            e = e4[c+3]; q = q4[c+3]; a3 += e.x*q.x + e.y*q.y + e.z*q.z + e.w*q.w;
        }
        lg[tid] = (a0 + a1) + (a2 + a3);
    }
    __syncthreads();

    const int warp = tid >> 5, lane = tid & 31;

    // ---- masked softmax per head (one warp per head) ----
    if (warp < HH) {
        int   m = 0;
        float v = -3.0e38f;
        if (lane < KKN) { m = ms[lane]; v = m ? lg[lane*4 + warp] : -3.0e38f; }
        float mx = v;
        #pragma unroll
        for (int off = 16; off; off >>= 1) mx = fmaxf(mx, __shfl_xor_sync(0xffffffffu, mx, off));
        float e   = (lane < KKN) ? expf(v - mx) : 0.f;
        float smv = e;
        #pragma unroll
        for (int off = 16; off; off >>= 1) smv += __shfl_xor_sync(0xffffffffu, smv, off);
        if (lane < KKN) ws[lane*4 + warp] = (e / smv) * (float)m;
    }
    __syncthreads();

    // ---- aggregation: Eagg[h][c] = sum_k w[k][h] * E[k][c] ----
    {
        const int c = tid;  // 0..255
        float acc0 = 0.f, acc1 = 0.f, acc2 = 0.f, acc3 = 0.f;
        #pragma unroll 5
        for (int k = 0; k < KKN; k++) {
            float4 w  = *(const float4*)&ws[k*4];
            float  ev = Es[k*EPITCH + c];
            acc0 += w.x * ev; acc1 += w.y * ev; acc2 += w.z * ev; acc3 += w.w * ev;
        }
        float* out = g_Eagg + (size_t)row * (HH*DIN);
        out[0*DIN + c] = acc0;
        out[1*DIN + c] = acc1;
        out[2*DIN + c] = acc2;
        out[3*DIN + c] = acc3;
    }
}

// ---------------------------------------------------------------------------
// Kernel 3: hu[r][h*32+j] = sum_c WV[h*32+j][c] * Eagg[r][h][c]
// 64 rows x 32 j (one head), 256 threads, acc[4][2], double-buffered.
// grid (125, 4 heads)
// ---------------------------------------------------------------------------
__global__ __launch_bounds__(256) void k3_vproj(const float* __restrict__ WV)
{
    __shared__ float as[64*33];
    __shared__ float bs[32*33];

    const int tid  = threadIdx.x;
    const int row0 = blockIdx.x * 64;
    const int h    = blockIdx.y;
    const int rt   = tid >> 4;
    const int jt   = tid & 15;

    const float* A  = g_Eagg + (size_t)h * DIN;
    const float* Bw = WV + (size_t)h * 32 * DIN;

    float ra[8], rb[4];
    #pragma unroll
    for (int it = 0; it < 8; it++) {
        int i = tid + 256*it;
        ra[it] = A[(size_t)(row0 + (i >> 5))*(HH*DIN) + (i & 31)];
    }
    #pragma unroll
    for (int it = 0; it < 4; it++) {
        int i = tid + 256*it;
        rb[it] = Bw[(size_t)(i >> 5)*DIN + (i & 31)];
    }

    float acc[4][2] = {};
    for (int cc = 0; cc < DIN; cc += 32) {
        __syncthreads();
        #pragma unroll
        for (int it = 0; it < 8; it++) {
            int i = tid + 256*it;
            as[(i >> 5)*33 + (i & 31)] = ra[it];
        }
        #pragma unroll
        for (int it = 0; it < 4; it++) {
            int i = tid + 256*it;
            bs[(i >> 5)*33 + (i & 31)] = rb[it];
        }
        __syncthreads();
        if (cc + 32 < DIN) {
            #pragma unroll
            for (int it = 0; it < 8; it++) {
                int i = tid + 256*it;
                ra[it] = A[(size_t)(row0 + (i >> 5))*(HH*DIN) + cc + 32 + (i & 31)];
            }
            #pragma unroll
            for (int it = 0; it < 4; it++) {
                int i = tid + 256*it;
                rb[it] = Bw[(size_t)(i >> 5)*DIN + cc + 32 + (i & 31)];
            }
        }
        #pragma unroll
        for (int c = 0; c < 32; c++) {
            float a[4], b[2];
            #pragma unroll
            for (int m = 0; m < 4; m++) a[m] = as[(rt + 16*m)*33 + c];
            #pragma unroll
            for (int n = 0; n < 2; n++) b[n] = bs[(jt + 16*n)*33 + c];
            #pragma unroll
            for (int m = 0; m < 4; m++)
                #pragma unroll
                for (int n = 0; n < 2; n++) acc[m][n] += a[m]*b[n];
        }
    }
    #pragma unroll
    for (int m = 0; m < 4; m++)
        #pragma unroll
        for (int n = 0; n < 2; n++)
            g_hu[(size_t)(row0 + rt + 16*m)*DD + h*32 + jt + 16*n] = acc[m][n];
}

// ---------------------------------------------------------------------------
// Kernel 4: out[r][o] = sum_d hu[r][d] * WO[o][d]
// 64 rows x 32 cols, grid (125, 4), double-buffered.
// ---------------------------------------------------------------------------
__global__ __launch_bounds__(256) void k4_out(const float* __restrict__ WO,
                                              float* __restrict__ out)
{
    __shared__ float as[64*33];
    __shared__ float bs[32*33];

    const int tid  = threadIdx.x;
    const int row0 = blockIdx.x * 64;
    const int col0 = blockIdx.y * 32;
    const int rt   = tid >> 4;
    const int jt   = tid & 15;

    float ra[8], rb[4];
    #pragma unroll
    for (int it = 0; it < 8; it++) {
        int i = tid + 256*it;
        ra[it] = g_hu[(size_t)(row0 + (i >> 5))*DD + (i & 31)];
    }
    #pragma unroll
    for (int it = 0; it < 4; it++) {
        int i = tid + 256*it;
        rb[it] = WO[(size_t)(col0 + (i >> 5))*DD + (i & 31)];
    }

    float acc[4][2] = {};
    for (int dc = 0; dc < DD; dc += 32) {
        __syncthreads();
        #pragma unroll
        for (int it = 0; it < 8; it++) {
            int i = tid + 256*it;
            as[(i >> 5)*33 + (i & 31)] = ra[it];
        }
        #pragma unroll
        for (int it = 0; it < 4; it++) {
            int i = tid + 256*it;
            bs[(i >> 5)*33 + (i & 31)] = rb[it];
        }
        __syncthreads();
        if (dc + 32 < DD) {
            #pragma unroll
            for (int it = 0; it < 8; it++) {
                int i = tid + 256*it;
                ra[it] = g_hu[(size_t)(row0 + (i >> 5))*DD + dc + 32 + (i & 31)];
            }
            #pragma unroll
            for (int it = 0; it < 4; it++) {
                int i = tid + 256*it;
                rb[it] = WO[(size_t)(col0 + (i >> 5))*DD + dc + 32 + (i & 31)];
            }
        }
        #pragma unroll
        for (int c = 0; c < 32; c++) {
            float a[4], b[2];
            #pragma unroll
            for (int m = 0; m < 4; m++) a[m] = as[(rt + 16*m)*33 + c];
            #pragma unroll
            for (int n = 0; n < 2; n++) b[n] = bs[(jt + 16*n)*33 + c];
            #pragma unroll
            for (int m = 0; m < 4; m++)
                #pragma unroll
                for (int n = 0; n < 2; n++) acc[m][n] += a[m]*b[n];
        }
    }
    #pragma unroll
    for (int m = 0; m < 4; m++)
        #pragma unroll
        for (int n = 0; n < 2; n++)
            out[(size_t)(row0 + rt + 16*m)*DD + col0 + jt + 16*n] = acc[m][n];
}

// ---------------------------------------------------------------------------
extern "C" void kernel_launch(void* const* d_in, const int* in_sizes, int n_in,
                              void* d_out, int out_size)
{
    const float* hV   = (const float*)d_in[0];
    const float* hE   = (const float*)d_in[1];
    const int*   mask = (const int*)  d_in[2];
    const float* WQ   = (const float*)d_in[3];
    const float* WK   = (const float*)d_in[4];
    const float* WV   = (const float*)d_in[5];
    const float* WO   = (const float*)d_in[6];
    float*       out  = (float*)d_out;

    kQ     <<<dim3(ROWS/64, 4),   256>>>(hV, WQ);
    kQp    <<<dim3(ROWS/64, HH),  256>>>(WK);
    k2_attn<<<ROWS,               256>>>(hE, mask);
    k3_vproj<<<dim3(ROWS/64, HH), 256>>>(WV);
    k4_out <<<dim3(ROWS/64, 4),   256>>>(WO, out);
}

// round 12
// speedup vs baseline: 1.4529x; 1.0191x over previous
#include <cuda_runtime.h>
#include <math.h>
#include <stdint.h>

// Problem constants
#define BB   4
#define NN   2000
#define KKN  30
#define DD   128
#define DIN  256
#define HH   4
#define ROWS (BB*NN)           // 8000

#define SCALE 0.17677669529663687f   // 1/sqrt(32)

#define EPITCH 260             // padded E row pitch (floats): conflict-free banks
#define QPITCH 260             // padded Q row pitch

// Scratch (static device globals: no runtime allocation)
__device__ float g_Qp  [(size_t)ROWS*HH*DIN];  // 32 MB  per-head K-projected query
__device__ float g_Eagg[(size_t)ROWS*HH*DIN];  // 32 MB  softmax-weighted E aggregate
__device__ float g_hu  [(size_t)ROWS*DD];      //  4 MB  per-head V projection

// ---------------------------------------------------------------------------
// Kernel QQp (fused): per head h, 64-row block.
//   Phase 1: Q_h[r][j] = sum_d hV[r][d] * WQ[h*32+j][d]     (into smem qs)
//   Phase 2: Qp[r][h*256+c] = SCALE * sum_j Q_h[r][j] * WK[h*32+j][c]
// grid (125, 4 heads), 256 threads.
// ---------------------------------------------------------------------------
__global__ __launch_bounds__(256) void kQQp(const float* __restrict__ hV,
                                            const float* __restrict__ WQ,
                                            const float* __restrict__ WK)
{
    __shared__ float as[64*33];    // hV chunk (64 x 32)
    __shared__ float bs[32*33];    // WQ chunk (32 j x 32 d)
    __shared__ float qs[64*33];    // Q_h tile (64 x 32)
    __shared__ float ws[32*65];    // WK chunk (32 j x 64 c)

    const int tid  = threadIdx.x;
    const int row0 = blockIdx.x * 64;
    const int h    = blockIdx.y;
    const int rt   = tid >> 4;   // 0..15
    const int jt   = tid & 15;   // 0..15

    // ---- Phase 1: Q_h = hV @ WQ_h^T (K=128, chunk 32), tile 64x32, acc[4][2]
    float acc[4][2] = {};
    for (int dc = 0; dc < DD; dc += 32) {
        __syncthreads();
        #pragma unroll
        for (int i = tid; i < 64*32; i += 256) {
            int r = i >> 5, c = i & 31;
            as[r*33 + c] = hV[(size_t)(row0 + r)*DD + dc + c];
        }
        #pragma unroll
        for (int i = tid; i < 32*32; i += 256) {
            int j = i >> 5, c = i & 31;
            bs[j*33 + c] = WQ[(size_t)(h*32 + j)*DD + dc + c];
        }
        __syncthreads();
        #pragma unroll
        for (int c = 0; c < 32; c++) {
            float a[4], b[2];
            #pragma unroll
            for (int m = 0; m < 4; m++) a[m] = as[(rt + 16*m)*33 + c];
            #pragma unroll
            for (int n = 0; n < 2; n++) b[n] = bs[(jt + 16*n)*33 + c];
            #pragma unroll
            for (int m = 0; m < 4; m++)
                #pragma unroll
                for (int n = 0; n < 2; n++) acc[m][n] += a[m]*b[n];
        }
    }
    __syncthreads();
    #pragma unroll
    for (int m = 0; m < 4; m++)
        #pragma unroll
        for (int n = 0; n < 2; n++)
            qs[(rt + 16*m)*33 + jt + 16*n] = acc[m][n];

    // ---- Phase 2: Qp = qs(64x32) @ WK_h(32x256), c chunked by 64, acc[4][4]
    const int ct = tid & 15;
    for (int cc = 0; cc < DIN; cc += 64) {
        __syncthreads();
        #pragma unroll
        for (int i = tid; i < 32*64; i += 256) {
            int j = i >> 6, c = i & 63;
            ws[j*65 + c] = WK[(size_t)(h*32 + j)*DIN + cc + c];
        }
        __syncthreads();

        float a2[4][4] = {};
        #pragma unroll
        for (int j = 0; j < 32; j++) {
            float a[4], b[4];
            #pragma unroll
            for (int m = 0; m < 4; m++) a[m] = qs[(rt + 16*m)*33 + j];
            #pragma unroll
            for (int n = 0; n < 4; n++) b[n] = ws[j*65 + ct + 16*n];
            #pragma unroll
            for (int m = 0; m < 4; m++)
                #pragma unroll
                for (int n = 0; n < 4; n++) a2[m][n] += a[m]*b[n];
        }
        #pragma unroll
        for (int m = 0; m < 4; m++)
            #pragma unroll
            for (int n = 0; n < 4; n++)
                g_Qp[(size_t)(row0 + rt + 16*m)*(HH*DIN) + h*DIN + cc + ct + 16*n]
                    = a2[m][n] * SCALE;
    }
}

// ---------------------------------------------------------------------------
// Kernel 2 (shuffle-free, split logits): one block per row, 256 threads.
// Logits split across two 120-thread groups (half the dot each):
//   group A: t in [0,120)    -> c [0,128)
//   group B: t in [128,248)  -> c [128,256)
// Each group keeps the t=k*4+h map -> 8 distinct k per warp, conflict-free.
// ---------------------------------------------------------------------------
__global__ __launch_bounds__(256) void k2_attn(const float* __restrict__ hE,
                                               const int*   __restrict__ mask)
{
    __shared__ __align__(16) float Es[KKN*EPITCH];  // 30x260
    __shared__ __align__(16) float Qs[HH*QPITCH];   // 4x260
    __shared__ float lp[2*120];                     // partial logits
    __shared__ float lg[128];                       // combined [k*4+h]
    __shared__ __align__(16) float ws[32*4];        // [k][h]
    __shared__ int   ms[32];

    const int tid = threadIdx.x;
    const int row = blockIdx.x;

    // Loads: Qp row + mask first (hide under E stream), then E tile (1920 float4)
    {
        if (tid < (HH*DIN)/4) {
            const float4* Qg = (const float4*)(g_Qp + (size_t)row * (HH*DIN));
            int h = tid >> 6, c4 = tid & 63;
            *(float4*)&Qs[h*QPITCH + c4*4] = Qg[tid];
        }
        if (tid < KKN) ms[tid] = mask[row*KKN + tid];

        const float4* Eg = (const float4*)(hE + (size_t)row * (KKN*DIN));
        #pragma unroll 4
        for (int i = tid; i < (KKN*DIN)/4; i += 256) {
            int k = i >> 6, c4 = i & 63;
            *(float4*)&Es[k*EPITCH + c4*4] = Eg[i];
        }
    }
    __syncthreads();

    // ---- logits: two groups, each thread does a 128-float private dot ----
    {
        const int grp = tid >> 7;          // 0 or 1
        const int t   = tid & 127;         // index within group
        if (t < 120) {
            const int k = t >> 2, h = t & 3;
            const float4* e4 = (const float4*)(Es + k*EPITCH) + grp*32;
            const float4* q4 = (const float4*)(Qs + h*QPITCH) + grp*32;
            float a0 = 0.f, a1 = 0.f, a2 = 0.f, a3 = 0.f;
            #pragma unroll
            for (int c = 0; c < 32; c += 4) {
                float4 e, q;
                e = e4[c+0]; q = q4[c+0]; a0 += e.x*q.x + e.y*q.y + e.z*q.z + e.w*q.w;
                e = e4[c+1]; q = q4[c+1]; a1 += e.x*q.x + e.y*q.y + e.z*q.z + e.w*q.w;
                e = e4[c+2]; q = q4[c+2]; a2 += e.x*q.x + e.y*q.y + e.z*q.z + e.w*q.w;
                e = e4[c+3]; q = q4[c+3]; a3 += e.x*q.x + e.y*q.y + e.z*q.z + e.w*q.w;
            }
            lp[grp*120 + t] = (a0 + a1) + (a2 + a3);
        }
    }
    __syncthreads();
    if (tid < 120) lg[tid] = lp[tid] + lp[120 + tid];
    __syncthreads();

    const int warp = tid >> 5, lane = tid & 31;

    // ---- masked softmax per head (one warp per head) ----
    if (warp < HH) {
        int   m = 0;
        float v = -3.0e38f;
        if (lane < KKN) { m = ms[lane]; v = m ? lg[lane*4 + warp] : -3.0e38f; }
        float mx = v;
        #pragma unroll
        for (int off = 16; off; off >>= 1) mx = fmaxf(mx, __shfl_xor_sync(0xffffffffu, mx, off));
        float e   = (lane < KKN) ? expf(v - mx) : 0.f;
        float smv = e;
        #pragma unroll
        for (int off = 16; off; off >>= 1) smv += __shfl_xor_sync(0xffffffffu, smv, off);
        if (lane < KKN) ws[lane*4 + warp] = (e / smv) * (float)m;
    }
    __syncthreads();

    // ---- aggregation: Eagg[h][c] = sum_k w[k][h] * E[k][c] ----
    {
        const int c = tid;  // 0..255
        float acc0 = 0.f, acc1 = 0.f, acc2 = 0.f, acc3 = 0.f;
        #pragma unroll 5
        for (int k = 0; k < KKN; k++) {
            float4 w  = *(const float4*)&ws[k*4];
            float  ev = Es[k*EPITCH + c];
            acc0 += w.x * ev; acc1 += w.y * ev; acc2 += w.z * ev; acc3 += w.w * ev;
        }
        float* out = g_Eagg + (size_t)row * (HH*DIN);
        out[0*DIN + c] = acc0;
        out[1*DIN + c] = acc1;
        out[2*DIN + c] = acc2;
        out[3*DIN + c] = acc3;
    }
}

// ---------------------------------------------------------------------------
// Kernel 3: hu[r][h*32+j] = sum_c WV[h*32+j][c] * Eagg[r][h][c]
// 64 rows x 32 j (one head), 256 threads, acc[4][2], double-buffered.
// grid (125, 4 heads)
// ---------------------------------------------------------------------------
__global__ __launch_bounds__(256) void k3_vproj(const float* __restrict__ WV)
{
    __shared__ float as[64*33];
    __shared__ float bs[32*33];

    const int tid  = threadIdx.x;
    const int row0 = blockIdx.x * 64;
    const int h    = blockIdx.y;
    const int rt   = tid >> 4;
    const int jt   = tid & 15;

    const float* A  = g_Eagg + (size_t)h * DIN;
    const float* Bw = WV + (size_t)h * 32 * DIN;

    float ra[8], rb[4];
    #pragma unroll
    for (int it = 0; it < 8; it++) {
        int i = tid + 256*it;
        ra[it] = A[(size_t)(row0 + (i >> 5))*(HH*DIN) + (i & 31)];
    }
    #pragma unroll
    for (int it = 0; it < 4; it++) {
        int i = tid + 256*it;
        rb[it] = Bw[(size_t)(i >> 5)*DIN + (i & 31)];
    }

    float acc[4][2] = {};
    for (int cc = 0; cc < DIN; cc += 32) {
        __syncthreads();
        #pragma unroll
        for (int it = 0; it < 8; it++) {
            int i = tid + 256*it;
            as[(i >> 5)*33 + (i & 31)] = ra[it];
        }
        #pragma unroll
        for (int it = 0; it < 4; it++) {
            int i = tid + 256*it;
            bs[(i >> 5)*33 + (i & 31)] = rb[it];
        }
        __syncthreads();
        if (cc + 32 < DIN) {
            #pragma unroll
            for (int it = 0; it < 8; it++) {
                int i = tid + 256*it;
                ra[it] = A[(size_t)(row0 + (i >> 5))*(HH*DIN) + cc + 32 + (i & 31)];
            }
            #pragma unroll
            for (int it = 0; it < 4; it++) {
                int i = tid + 256*it;
                rb[it] = Bw[(size_t)(i >> 5)*DIN + cc + 32 + (i & 31)];
            }
        }
        #pragma unroll
        for (int c = 0; c < 32; c++) {
            float a[4], b[2];
            #pragma unroll
            for (int m = 0; m < 4; m++) a[m] = as[(rt + 16*m)*33 + c];
            #pragma unroll
            for (int n = 0; n < 2; n++) b[n] = bs[(jt + 16*n)*33 + c];
            #pragma unroll
            for (int m = 0; m < 4; m++)
                #pragma unroll
                for (int n = 0; n < 2; n++) acc[m][n] += a[m]*b[n];
        }
    }
    #pragma unroll
    for (int m = 0; m < 4; m++)
        #pragma unroll
        for (int n = 0; n < 2; n++)
            g_hu[(size_t)(row0 + rt + 16*m)*DD + h*32 + jt + 16*n] = acc[m][n];
}

// ---------------------------------------------------------------------------
// Kernel 4: out[r][o] = sum_d hu[r][d] * WO[o][d]
// 64 rows x 32 cols, grid (125, 4), double-buffered.
// ---------------------------------------------------------------------------
__global__ __launch_bounds__(256) void k4_out(const float* __restrict__ WO,
                                              float* __restrict__ out)
{
    __shared__ float as[64*33];
    __shared__ float bs[32*33];

    const int tid  = threadIdx.x;
    const int row0 = blockIdx.x * 64;
    const int col0 = blockIdx.y * 32;
    const int rt   = tid >> 4;
    const int jt   = tid & 15;

    float ra[8], rb[4];
    #pragma unroll
    for (int it = 0; it < 8; it++) {
        int i = tid + 256*it;
        ra[it] = g_hu[(size_t)(row0 + (i >> 5))*DD + (i & 31)];
    }
    #pragma unroll
    for (int it = 0; it < 4; it++) {
        int i = tid + 256*it;
        rb[it] = WO[(size_t)(col0 + (i >> 5))*DD + (i & 31)];
    }

    float acc[4][2] = {};
    for (int dc = 0; dc < DD; dc += 32) {
        __syncthreads();
        #pragma unroll
        for (int it = 0; it < 8; it++) {
            int i = tid + 256*it;
            as[(i >> 5)*33 + (i & 31)] = ra[it];
        }
        #pragma unroll
        for (int it = 0; it < 4; it++) {
            int i = tid + 256*it;
            bs[(i >> 5)*33 + (i & 31)] = rb[it];
        }
        __syncthreads();
        if (dc + 32 < DD) {
            #pragma unroll
            for (int it = 0; it < 8; it++) {
                int i = tid + 256*it;
                ra[it] = g_hu[(size_t)(row0 + (i >> 5))*DD + dc + 32 + (i & 31)];
            }
            #pragma unroll
            for (int it = 0; it < 4; it++) {
                int i = tid + 256*it;
                rb[it] = WO[(size_t)(col0 + (i >> 5))*DD + dc + 32 + (i & 31)];
            }
        }
        #pragma unroll
        for (int c = 0; c < 32; c++) {
            float a[4], b[2];
            #pragma unroll
            for (int m = 0; m < 4; m++) a[m] = as[(rt + 16*m)*33 + c];
            #pragma unroll
            for (int n = 0; n < 2; n++) b[n] = bs[(jt + 16*n)*33 + c];
            #pragma unroll
            for (int m = 0; m < 4; m++)
                #pragma unroll
                for (int n = 0; n < 2; n++) acc[m][n] += a[m]*b[n];
        }
    }
    #pragma unroll
    for (int m = 0; m < 4; m++)
        #pragma unroll
        for (int n = 0; n < 2; n++)
            out[(size_t)(row0 + rt + 16*m)*DD + col0 + jt + 16*n] = acc[m][n];
}

// ---------------------------------------------------------------------------
extern "C" void kernel_launch(void* const* d_in, const int* in_sizes, int n_in,
                              void* d_out, int out_size)
{
    const float* hV   = (const float*)d_in[0];
    const float* hE   = (const float*)d_in[1];
    const int*   mask = (const int*)  d_in[2];
    const float* WQ   = (const float*)d_in[3];
    const float* WK   = (const float*)d_in[4];
    const float* WV   = (const float*)d_in[5];
    const float* WO   = (const float*)d_in[6];
    float*       out  = (float*)d_out;

    kQQp   <<<dim3(ROWS/64, HH),  256>>>(hV, WQ, WK);
    k2_attn<<<ROWS,               256>>>(hE, mask);
    k3_vproj<<<dim3(ROWS/64, HH), 256>>>(WV);
    k4_out <<<dim3(ROWS/64, 4),   256>>>(WO, out);
}